// round 7
// baseline (speedup 1.0000x reference)
#include <cuda_runtime.h>
#include <cuda_fp16.h>
#include <cstdint>

#define NN 50000
#define NNP 50048            /* padded to grid*128 */
#define NE 800000
#define NE2 850000           /* NE + NN self loops */
#define NG 64

// ---------------- device scratch (no allocations; zero-init padding) -------
__device__ __align__(16) __half g_x16[(size_t)NNP * 128];     // activations fp16
__device__ __align__(16) __half g_agg[(size_t)NNP * 512];     // per-head aggregated x
__device__ __align__(16) float g_als[NN * 4];
__device__ __align__(16) float g_ald[NN * 4];
__device__ __align__(16) float g_alpha[NE2 * 4];
__device__ __align__(16) __half g_wphi[64 * 512];             // W' hi  [c][h*K+k]
__device__ __align__(16) __half g_wplo[64 * 512];             // W' lo*1024
__device__ __align__(16) float g_cvec[3 * 8 * 128];           // C vectors [l][slot][k]
__device__ int   g_deg[NN];
__device__ int   g_offs[NN + 1];
__device__ int   g_cursor[NN];
__device__ int   g_ssrc[NE2];
__device__ float g_psum[NG * 64];
__device__ float g_pcnt[NG];

// ---------------- CSR build ----------------
__global__ void k_init() {
  int i = blockIdx.x * blockDim.x + threadIdx.x;
  if (i < NN) g_deg[i] = 1;
  if (i < NG * 64) g_psum[i] = 0.f;
  if (i < NG) g_pcnt[i] = 0.f;
}

__global__ void k_degree(const int* __restrict__ ei) {
  int e = blockIdx.x * blockDim.x + threadIdx.x;
  if (e < NE) atomicAdd(&g_deg[ei[NE + e]], 1);
}

__global__ void k_scan() {
  __shared__ int sums[1024];
  const int CH = (NN + 1023) / 1024;
  int t = threadIdx.x;
  int base = t * CH;
  int s = 0;
  for (int i = 0; i < CH; i++) { int idx = base + i; if (idx < NN) s += g_deg[idx]; }
  sums[t] = s;
  __syncthreads();
  for (int off = 1; off < 1024; off <<= 1) {
    int v = (t >= off) ? sums[t - off] : 0;
    __syncthreads();
    sums[t] += v;
    __syncthreads();
  }
  int run = (t == 0) ? 0 : sums[t - 1];
  for (int i = 0; i < CH; i++) {
    int idx = base + i;
    if (idx < NN) { g_offs[idx] = run; g_cursor[idx] = run; run += g_deg[idx]; }
  }
  if (t == 0) g_offs[NN] = sums[1023];
}

__global__ void k_scatter(const int* __restrict__ ei) {
  int e = blockIdx.x * blockDim.x + threadIdx.x;
  if (e >= NE2) return;
  int s, d;
  if (e < NE) { s = ei[e]; d = ei[NE + e]; }
  else        { s = e - NE; d = s; }
  int pos = atomicAdd(&g_cursor[d], 1);
  g_ssrc[pos] = s;
}

// ---------------- C vectors: C[l][slot][k] = sum_c W_l[k][h*64+c]*a[h][c] ----
// slot = is_dst*4 + h
__global__ void k_cvecs(const float* __restrict__ W1, const float* __restrict__ as1, const float* __restrict__ ad1,
                        const float* __restrict__ W2, const float* __restrict__ as2, const float* __restrict__ ad2,
                        const float* __restrict__ W3, const float* __restrict__ as3, const float* __restrict__ ad3) {
  int id = blockIdx.x * blockDim.x + threadIdx.x;
  if (id >= 2048) return;
  int l, K, off;
  if (id < 1024)      { l = 0; K = 128; off = id; }
  else if (id < 1536) { l = 1; K = 64;  off = id - 1024; }
  else                { l = 2; K = 64;  off = id - 1536; }
  int slot = off / K, k = off - slot * K;
  int h = slot & 3;
  const float* W = (l == 0) ? W1 : (l == 1) ? W2 : W3;
  const float* a = (slot >= 4) ? ((l == 0) ? ad1 : (l == 1) ? ad2 : ad3)
                               : ((l == 0) ? as1 : (l == 1) ? as2 : as3);
  float s = 0.f;
#pragma unroll 8
  for (int c = 0; c < 64; c++)
    s = fmaf(W[k * 256 + h * 64 + c], a[h * 64 + c], s);
  g_cvec[l * 1024 + slot * 128 + k] = s;
}

// ---------------- x -> fp16 ----------------
__global__ void k_xprep(const float* __restrict__ x) {
  int i = blockIdx.x * blockDim.x + threadIdx.x;   // half2 units, NN*64 of them
  if (i >= NN * 64) return;
  float2 v = *(const float2*)(x + (size_t)i * 2);
  *((__half2*)g_x16 + i) = __floats2half2_rn(v.x, v.y);
}

// ---------------- W' split: [c][h*K+k] = W[k][h*64+c]*0.25, fp16 hi + lo*1024
__global__ void k_wprep(const float* __restrict__ W, int K) {
  int KK = 4 * K;
  int idx = blockIdx.x * blockDim.x + threadIdx.x;
  if (idx >= 64 * KK) return;
  int cc = idx / KK, hk = idx - cc * KK;
  int h = hk / K, k = hk - h * K;
  float w = W[k * 256 + h * 64 + cc] * 0.25f;
  __half hi = __float2half_rn(w);
  __half lo = __float2half_rn((w - __half2float(hi)) * 1024.0f);
  g_wphi[idx] = hi;
  g_wplo[idx] = lo;
}

// ---------------- attention logits from x: als/ald = x . C ----------------
__global__ void __launch_bounds__(256)
k_logits(int l, int K) {
  int w = (blockIdx.x * blockDim.x + threadIdx.x) >> 5;
  int lane = threadIdx.x & 31;
  if (w >= NN) return;
  const float* C = g_cvec + l * 1024;
  float p[8];
#pragma unroll
  for (int t = 0; t < 8; t++) p[t] = 0.f;

  if (K == 64) {
    __half2 xv = __ldg((const __half2*)(g_x16 + (size_t)w * 64) + lane);
    float2 xf = __half22float2(xv);
#pragma unroll
    for (int t = 0; t < 8; t++) {
      float2 c2 = *(const float2*)(C + t * 128 + 2 * lane);
      p[t] = fmaf(xf.x, c2.x, xf.y * c2.y);
    }
  } else {
    __half2 xv0 = __ldg((const __half2*)(g_x16 + (size_t)w * 128) + lane);
    __half2 xv1 = __ldg((const __half2*)(g_x16 + (size_t)w * 128) + 32 + lane);
    float2 f0 = __half22float2(xv0);
    float2 f1 = __half22float2(xv1);
#pragma unroll
    for (int t = 0; t < 8; t++) {
      float2 c0 = *(const float2*)(C + t * 128 + 2 * lane);
      float2 c1 = *(const float2*)(C + t * 128 + 64 + 2 * lane);
      p[t] = fmaf(f0.x, c0.x, fmaf(f0.y, c0.y, fmaf(f1.x, c1.x, f1.y * c1.y)));
    }
  }
#pragma unroll
  for (int o = 16; o; o >>= 1)
#pragma unroll
    for (int t = 0; t < 8; t++) p[t] += __shfl_xor_sync(0xffffffffu, p[t], o);
  if (lane == 0) {
    *(float4*)(g_als + w * 4) = make_float4(p[0], p[1], p[2], p[3]);
    *(float4*)(g_ald + w * 4) = make_float4(p[4], p[5], p[6], p[7]);
  }
}

// ---------------- softmax + x-aggregation: one warp per dst node -----------
// Max-shift skipped: logits are O(1) by construction -> exp cannot overflow.
__device__ __forceinline__ float leaky(float v) { return v >= 0.f ? v : 0.2f * v; }

__global__ void __launch_bounds__(256)
k_aggx(int K) {
  int warp = (blockIdx.x * blockDim.x + threadIdx.x) >> 5;
  int lane = threadIdx.x & 31;
  if (warp >= NN) return;
  const int n = warp;
  const int beg = g_offs[n], end = g_offs[n + 1];
  const float4 ald = *(const float4*)&g_ald[n * 4];

  float d0 = 0.f, d1 = 0.f, d2 = 0.f, d3 = 0.f;
  for (int e = beg + lane; e < end; e += 32) {
    int s = g_ssrc[e];
    float4 als = *(const float4*)&g_als[s * 4];
    float p0 = __expf(leaky(als.x + ald.x));
    float p1 = __expf(leaky(als.y + ald.y));
    float p2 = __expf(leaky(als.z + ald.z));
    float p3 = __expf(leaky(als.w + ald.w));
    d0 += p0; d1 += p1; d2 += p2; d3 += p3;
    *(float4*)&g_alpha[(size_t)e * 4] = make_float4(p0, p1, p2, p3);
  }
#pragma unroll
  for (int o = 16; o; o >>= 1) {
    d0 += __shfl_xor_sync(0xffffffffu, d0, o);
    d1 += __shfl_xor_sync(0xffffffffu, d1, o);
    d2 += __shfl_xor_sync(0xffffffffu, d2, o);
    d3 += __shfl_xor_sync(0xffffffffu, d3, o);
  }
  __syncwarp();
  float r0 = 1.0f / d0, r1 = 1.0f / d1, r2 = 1.0f / d2, r3 = 1.0f / d3;

  if (K == 64) {
    float2 acc[4];
#pragma unroll
    for (int h = 0; h < 4; h++) acc[h] = make_float2(0.f, 0.f);
    for (int e = beg; e < end; ++e) {
      int s = g_ssrc[e];
      float4 p = *(const float4*)&g_alpha[(size_t)e * 4];
      float w0 = p.x * r0, w1 = p.y * r1, w2 = p.z * r2, w3 = p.w * r3;
      __half2 xv = __ldg((const __half2*)(g_x16 + (size_t)s * 64) + lane);
      float2 xf = __half22float2(xv);
      acc[0].x = fmaf(w0, xf.x, acc[0].x); acc[0].y = fmaf(w0, xf.y, acc[0].y);
      acc[1].x = fmaf(w1, xf.x, acc[1].x); acc[1].y = fmaf(w1, xf.y, acc[1].y);
      acc[2].x = fmaf(w2, xf.x, acc[2].x); acc[2].y = fmaf(w2, xf.y, acc[2].y);
      acc[3].x = fmaf(w3, xf.x, acc[3].x); acc[3].y = fmaf(w3, xf.y, acc[3].y);
    }
#pragma unroll
    for (int h = 0; h < 4; h++)
      *((__half2*)(g_agg + (size_t)n * 256 + h * 64) + lane) =
          __floats2half2_rn(acc[h].x, acc[h].y);
  } else {
    float2 accA[4], accB[4];
#pragma unroll
    for (int h = 0; h < 4; h++) { accA[h] = make_float2(0.f, 0.f); accB[h] = make_float2(0.f, 0.f); }
    for (int e = beg; e < end; ++e) {
      int s = g_ssrc[e];
      float4 p = *(const float4*)&g_alpha[(size_t)e * 4];
      float w0 = p.x * r0, w1 = p.y * r1, w2 = p.z * r2, w3 = p.w * r3;
      uint2 rxy = __ldg((const uint2*)(g_x16 + (size_t)s * 128) + lane);
      float2 fA = __half22float2(*(const __half2*)&rxy.x);
      float2 fB = __half22float2(*(const __half2*)&rxy.y);
      accA[0].x = fmaf(w0, fA.x, accA[0].x); accA[0].y = fmaf(w0, fA.y, accA[0].y);
      accB[0].x = fmaf(w0, fB.x, accB[0].x); accB[0].y = fmaf(w0, fB.y, accB[0].y);
      accA[1].x = fmaf(w1, fA.x, accA[1].x); accA[1].y = fmaf(w1, fA.y, accA[1].y);
      accB[1].x = fmaf(w1, fB.x, accB[1].x); accB[1].y = fmaf(w1, fB.y, accB[1].y);
      accA[2].x = fmaf(w2, fA.x, accA[2].x); accA[2].y = fmaf(w2, fA.y, accA[2].y);
      accB[2].x = fmaf(w2, fB.x, accB[2].x); accB[2].y = fmaf(w2, fB.y, accB[2].y);
      accA[3].x = fmaf(w3, fA.x, accA[3].x); accA[3].y = fmaf(w3, fA.y, accA[3].y);
      accB[3].x = fmaf(w3, fB.x, accB[3].x); accB[3].y = fmaf(w3, fB.y, accB[3].y);
    }
#pragma unroll
    for (int h = 0; h < 4; h++) {
      uint2 outv;
      *(__half2*)&outv.x = __floats2half2_rn(accA[h].x, accA[h].y);
      *(__half2*)&outv.y = __floats2half2_rn(accB[h].x, accB[h].y);
      *((uint2*)(g_agg + (size_t)n * 512 + h * 128) + lane) = outv;
    }
  }
}

// ---------------- GEMM2: out[N,64] = agg[N,KK] @ W'[KK,64] + bias (+relu) ---
__device__ __forceinline__ void mma_f16(float* c, const uint32_t* a, uint32_t b0, uint32_t b1) {
  asm volatile(
      "mma.sync.aligned.m16n8k16.row.col.f32.f16.f16.f32 "
      "{%0,%1,%2,%3}, {%4,%5,%6,%7}, {%8,%9}, {%0,%1,%2,%3};\n"
      : "+f"(c[0]), "+f"(c[1]), "+f"(c[2]), "+f"(c[3])
      : "r"(a[0]), "r"(a[1]), "r"(a[2]), "r"(a[3]), "r"(b0), "r"(b1));
}

__device__ __forceinline__ uint32_t sm_u32(const void* p) {
  return (uint32_t)__cvta_generic_to_shared(p);
}
#define CPA16(dst, src) \
  asm volatile("cp.async.cg.shared.global [%0], [%1], 16;" ::"r"(dst), "l"(src))

__global__ void __launch_bounds__(256, 2)
k_gemm2(int KK, const float* __restrict__ bias, int final_, float* __restrict__ emb) {
  __shared__ __align__(16) __half sA[2][128 * 40];
  __shared__ __align__(16) __half sBh[2][64 * 40];
  __shared__ __align__(16) __half sBl[2][64 * 40];

  const int bm = blockIdx.x * 128;
  const int tid = threadIdx.x;
  const int warp = tid >> 5, lane = tid & 31;
  const int gid = lane >> 2, tig = lane & 3;
  const int nc = KK >> 5;

  float accH[8][4], accL[8][4];
#pragma unroll
  for (int j = 0; j < 8; j++)
#pragma unroll
    for (int q = 0; q < 4; q++) { accH[j][q] = 0.f; accL[j][q] = 0.f; }

  auto stage = [&](int c, int b) {
#pragma unroll
    for (int rep = 0; rep < 2; rep++) {
      int i = tid + rep * 256;
      int row = i >> 2, o16 = i & 3;
      const __half* src = g_agg + (size_t)(bm + row) * KK + c * 32 + o16 * 8;
      CPA16(sm_u32(&sA[b][row * 40 + o16 * 8]), src);
    }
    {
      int row = tid >> 2, o16 = tid & 3;
      CPA16(sm_u32(&sBh[b][row * 40 + o16 * 8]), g_wphi + row * KK + c * 32 + o16 * 8);
      CPA16(sm_u32(&sBl[b][row * 40 + o16 * 8]), g_wplo + row * KK + c * 32 + o16 * 8);
    }
    asm volatile("cp.async.commit_group;");
  };

  stage(0, 0);
  for (int c = 0; c < nc; c++) {
    int b = c & 1;
    if (c + 1 < nc) {
      stage(c + 1, b ^ 1);
      asm volatile("cp.async.wait_group 1;");
    } else {
      asm volatile("cp.async.wait_group 0;");
    }
    __syncthreads();
#pragma unroll
    for (int ks = 0; ks < 2; ks++) {
      const int kb = ks * 16;
      uint32_t a[4];
      const __half* pa = &sA[b][(warp * 16 + gid) * 40 + kb + 2 * tig];
      a[0] = *(const uint32_t*)pa;
      a[1] = *(const uint32_t*)(pa + 8 * 40);
      a[2] = *(const uint32_t*)(pa + 8);
      a[3] = *(const uint32_t*)(pa + 8 * 40 + 8);
#pragma unroll
      for (int j = 0; j < 8; j++) {
        const __half* pb = &sBh[b][(j * 8 + gid) * 40 + kb + 2 * tig];
        const __half* pl = &sBl[b][(j * 8 + gid) * 40 + kb + 2 * tig];
        mma_f16(accH[j], a, *(const uint32_t*)pb, *(const uint32_t*)(pb + 8));
        mma_f16(accL[j], a, *(const uint32_t*)pl, *(const uint32_t*)(pl + 8));
      }
    }
    __syncthreads();
  }

  // epilogue: combine hi + lo/1024, add bias, relu or final write
  const int row0 = bm + warp * 16 + gid;
  const int row1 = row0 + 8;
#pragma unroll
  for (int j = 0; j < 8; j++) {
    int col = j * 8 + 2 * tig;
    float bx = __ldg(bias + col), by = __ldg(bias + col + 1);
    float v0 = accH[j][0] + accL[j][0] * (1.0f / 1024.0f) + bx;
    float v1 = accH[j][1] + accL[j][1] * (1.0f / 1024.0f) + by;
    float v2 = accH[j][2] + accL[j][2] * (1.0f / 1024.0f) + bx;
    float v3 = accH[j][3] + accL[j][3] * (1.0f / 1024.0f) + by;
    if (final_) {
      if (row0 < NN) *(float2*)(emb + (size_t)row0 * 64 + col) = make_float2(v0, v1);
      if (row1 < NN) *(float2*)(emb + (size_t)row1 * 64 + col) = make_float2(v2, v3);
    } else {
      v0 = fmaxf(v0, 0.f); v1 = fmaxf(v1, 0.f);
      v2 = fmaxf(v2, 0.f); v3 = fmaxf(v3, 0.f);
      if (row0 < NN) *(__half2*)(g_x16 + (size_t)row0 * 64 + col) = __floats2half2_rn(v0, v1);
      if (row1 < NN) *(__half2*)(g_x16 + (size_t)row1 * 64 + col) = __floats2half2_rn(v2, v3);
    }
  }
}

// ---------------- node MLP heads + pooling ----------------
__device__ __forceinline__ float sigmoidf_(float x) { return 1.0f / (1.0f + __expf(-x)); }

__global__ void k_node_mlp(const float* __restrict__ emb, const int* __restrict__ batch,
                           const float* __restrict__ aw1, const float* __restrict__ ab1,
                           const float* __restrict__ aw2, const float* __restrict__ ab2,
                           const float* __restrict__ rw1, const float* __restrict__ rb1,
                           const float* __restrict__ rw2, const float* __restrict__ rb2,
                           const float* __restrict__ cw1, const float* __restrict__ cb1,
                           const float* __restrict__ cw2, const float* __restrict__ cb2,
                           float* __restrict__ anomaly, float* __restrict__ risk,
                           float* __restrict__ resource) {
  int warp = (blockIdx.x * blockDim.x + threadIdx.x) >> 5;
  int lane = threadIdx.x & 31;
  if (warp >= NN) return;
  int n = warp;
  float e0 = emb[(size_t)n * 64 + lane];
  float e1 = emb[(size_t)n * 64 + 32 + lane];

  float ha = ab1[lane], hr = rb1[lane], hc = cb1[lane];
#pragma unroll
  for (int k = 0; k < 32; k++) {
    float ek = __shfl_sync(0xffffffffu, e0, k);
    ha = fmaf(ek, aw1[k * 32 + lane], ha);
    hr = fmaf(ek, rw1[k * 32 + lane], hr);
    hc = fmaf(ek, cw1[k * 32 + lane], hc);
  }
#pragma unroll
  for (int k = 0; k < 32; k++) {
    float ek = __shfl_sync(0xffffffffu, e1, k);
    ha = fmaf(ek, aw1[(k + 32) * 32 + lane], ha);
    hr = fmaf(ek, rw1[(k + 32) * 32 + lane], hr);
    hc = fmaf(ek, cw1[(k + 32) * 32 + lane], hc);
  }
  ha = fmaxf(ha, 0.f); hr = fmaxf(hr, 0.f); hc = fmaxf(hc, 0.f);

  float va = ha * aw2[lane];
  float vr = hr * rw2[lane];
#pragma unroll
  for (int o = 16; o; o >>= 1) {
    va += __shfl_xor_sync(0xffffffffu, va, o);
    vr += __shfl_xor_sync(0xffffffffu, vr, o);
  }
  if (lane == 0) {
    anomaly[n] = sigmoidf_(va + ab2[0]);
    risk[n]    = sigmoidf_(vr + rb2[0]);
  }
#pragma unroll
  for (int o5 = 0; o5 < 5; o5++) {
    float vc = hc * cw2[lane * 5 + o5];
#pragma unroll
    for (int o = 16; o; o >>= 1) vc += __shfl_xor_sync(0xffffffffu, vc, o);
    if (lane == 0) resource[(size_t)n * 5 + o5] = vc + cb2[o5];
  }

  int g = batch[n];
  atomicAdd(&g_psum[g * 64 + lane], e0);
  atomicAdd(&g_psum[g * 64 + 32 + lane], e1);
  if (lane == 0) atomicAdd(&g_pcnt[g], 1.0f);
}

__global__ void k_graph_head(const float* __restrict__ gw1, const float* __restrict__ gb1,
                             const float* __restrict__ gw2, const float* __restrict__ gb2,
                             float* __restrict__ glog) {
  int g = blockIdx.x;
  int lane = threadIdx.x;
  float rc = 1.0f / fmaxf(g_pcnt[g], 1.0f);
  float hid = gb1[lane];
#pragma unroll
  for (int c = 0; c < 64; c++)
    hid = fmaf(g_psum[g * 64 + c] * rc, gw1[c * 32 + lane], hid);
  hid = fmaxf(hid, 0.f);
#pragma unroll
  for (int o4 = 0; o4 < 4; o4++) {
    float v = hid * gw2[lane * 4 + o4];
#pragma unroll
    for (int o = 16; o; o >>= 1) v += __shfl_xor_sync(0xffffffffu, v, o);
    if (lane == 0) glog[g * 4 + o4] = v + gb2[o4];
  }
}

// ---------------- launch ----------------
extern "C" void kernel_launch(void* const* d_in, const int* in_sizes, int n_in,
                              void* d_out, int out_size) {
  const float* x    = (const float*)d_in[0];
  const int*   ei   = (const int*)d_in[1];
  const int*   batch= (const int*)d_in[2];
  const float* W1   = (const float*)d_in[3];
  const float* as1  = (const float*)d_in[4];
  const float* ad1  = (const float*)d_in[5];
  const float* b1   = (const float*)d_in[6];
  const float* W2   = (const float*)d_in[7];
  const float* as2  = (const float*)d_in[8];
  const float* ad2  = (const float*)d_in[9];
  const float* b2   = (const float*)d_in[10];
  const float* W3   = (const float*)d_in[11];
  const float* as3  = (const float*)d_in[12];
  const float* ad3  = (const float*)d_in[13];
  const float* b3   = (const float*)d_in[14];
  const float* aw1  = (const float*)d_in[15];
  const float* ab1  = (const float*)d_in[16];
  const float* aw2  = (const float*)d_in[17];
  const float* ab2  = (const float*)d_in[18];
  const float* rw1  = (const float*)d_in[19];
  const float* rb1  = (const float*)d_in[20];
  const float* rw2  = (const float*)d_in[21];
  const float* rb2  = (const float*)d_in[22];
  const float* cw1  = (const float*)d_in[23];
  const float* cb1  = (const float*)d_in[24];
  const float* cw2  = (const float*)d_in[25];
  const float* cb2  = (const float*)d_in[26];
  const float* gw1  = (const float*)d_in[27];
  const float* gb1  = (const float*)d_in[28];
  const float* gw2  = (const float*)d_in[29];
  const float* gb2  = (const float*)d_in[30];

  float* out      = (float*)d_out;
  float* emb      = out;                        // N*64
  float* anomaly  = out + (size_t)NN * 64;      // N
  float* risk     = anomaly + NN;               // N
  float* resource = risk + NN;                  // N*5
  float* glog     = resource + (size_t)NN * 5;  // G*4

  int agg_grid = (NN * 32 + 255) / 256;
  int lg_grid  = (NN + 7) / 8;                  // 8 warps/block
  int gemm_grid = NNP / 128;                    // 391

  // prep + CSR
  k_init<<<(NN + 255) / 256, 256>>>();
  k_degree<<<(NE + 255) / 256, 256>>>(ei);
  k_cvecs<<<8, 256>>>(W1, as1, ad1, W2, as2, ad2, W3, as3, ad3);
  k_xprep<<<(NN * 64 + 255) / 256, 256>>>(x);
  k_scan<<<1, 1024>>>();
  k_scatter<<<(NE2 + 255) / 256, 256>>>(ei);

  // layer 1 (x K=128, agg KK=512)
  k_logits<<<lg_grid, 256>>>(0, 128);
  k_wprep<<<(64 * 512 + 255) / 256, 256>>>(W1, 128);
  k_aggx<<<agg_grid, 256>>>(128);
  k_gemm2<<<gemm_grid, 256>>>(512, b1, 0, nullptr);
  // layer 2 (x K=64, agg KK=256)
  k_logits<<<lg_grid, 256>>>(1, 64);
  k_wprep<<<(64 * 256 + 255) / 256, 256>>>(W2, 64);
  k_aggx<<<agg_grid, 256>>>(64);
  k_gemm2<<<gemm_grid, 256>>>(256, b2, 0, nullptr);
  // layer 3
  k_logits<<<lg_grid, 256>>>(2, 64);
  k_wprep<<<(64 * 256 + 255) / 256, 256>>>(W3, 64);
  k_aggx<<<agg_grid, 256>>>(64);
  k_gemm2<<<gemm_grid, 256>>>(256, b3, 1, emb);

  // heads
  k_node_mlp<<<agg_grid, 256>>>(emb, batch, aw1, ab1, aw2, ab2,
                                rw1, rb1, rw2, rb2, cw1, cb1, cw2, cb2,
                                anomaly, risk, resource);
  k_graph_head<<<NG, 32>>>(gw1, gb1, gw2, gb2, glog);
}

// round 8
// speedup vs baseline: 1.1177x; 1.1177x over previous
#include <cuda_runtime.h>
#include <cuda_bf16.h>
#include <cuda_fp16.h>
#include <cstdint>

#define NN 50000
#define NE 800000
#define NE2 850000   /* NE + NN self loops */
#define NG 64

// ---------------- device scratch (no allocations allowed) ----------------
__device__ __align__(16) __half g_h16[NN * 256]; // per-layer h = x@W  [N, H*C] fp16
__device__ __align__(16) float g_x[NN * 64];    // layer activation buffer [N, 64]
__device__ __align__(16) float g_als[NN * 4];
__device__ __align__(16) float g_ald[NN * 4];
__device__ __align__(16) float g_alpha[NE2 * 4]; // overflow fallback only
__device__ __align__(16) __nv_bfloat16 g_bthi[256 * 128]; // W^T split hi [n][k]
__device__ __align__(16) __nv_bfloat16 g_btlo[256 * 128]; // W^T split lo [n][k]
__device__ int   g_deg[NN];
__device__ int   g_offs[NN + 1];
__device__ int   g_cursor[NN];
__device__ int   g_ssrc[NE2];
__device__ float g_psum[NG * 64];
__device__ float g_pcnt[NG];

// ---------------- CSR build ----------------
__global__ void k_init() {
  int i = blockIdx.x * blockDim.x + threadIdx.x;
  if (i < NN) g_deg[i] = 1;              // self-loop pre-counted
  if (i < NG * 64) g_psum[i] = 0.f;
  if (i < NG) g_pcnt[i] = 0.f;
}

__global__ void k_degree(const int* __restrict__ ei) {
  int e = blockIdx.x * blockDim.x + threadIdx.x;
  if (e < NE) atomicAdd(&g_deg[ei[NE + e]], 1);
}

__global__ void k_scan() {
  __shared__ int sums[1024];
  const int CH = (NN + 1023) / 1024;   // 49
  int t = threadIdx.x;
  int base = t * CH;
  int s = 0;
  for (int i = 0; i < CH; i++) { int idx = base + i; if (idx < NN) s += g_deg[idx]; }
  sums[t] = s;
  __syncthreads();
  for (int off = 1; off < 1024; off <<= 1) {
    int v = (t >= off) ? sums[t - off] : 0;
    __syncthreads();
    sums[t] += v;
    __syncthreads();
  }
  int run = (t == 0) ? 0 : sums[t - 1];
  for (int i = 0; i < CH; i++) {
    int idx = base + i;
    if (idx < NN) { g_offs[idx] = run; g_cursor[idx] = run; run += g_deg[idx]; }
  }
  if (t == 0) g_offs[NN] = sums[1023];
}

__global__ void k_scatter(const int* __restrict__ ei) {
  int e = blockIdx.x * blockDim.x + threadIdx.x;
  if (e >= NE2) return;
  int s, d;
  if (e < NE) { s = ei[e]; d = ei[NE + e]; }
  else        { s = e - NE; d = s; }
  int pos = atomicAdd(&g_cursor[d], 1);
  g_ssrc[pos] = s;
}

// ---------------- W split+transpose: W[K][256] fp32 -> g_bthi/lo [256][K] bf16 ----
__global__ void k_bsplit(const float* __restrict__ W, int K) {
  int idx = blockIdx.x * blockDim.x + threadIdx.x;
  if (idx >= 256 * K) return;
  int n = idx / K, k = idx - n * K;
  float v = W[k * 256 + n];
  __nv_bfloat16 hi = __float2bfloat16(v);
  __nv_bfloat16 lo = __float2bfloat16(v - __bfloat162float(hi));
  g_bthi[idx] = hi;
  g_btlo[idx] = lo;
}

// ---------------- tensor-core GEMM + fused attention logits ----------------
__device__ __forceinline__ void mma_bf16(float* c, const uint32_t* a, uint32_t b0, uint32_t b1) {
  asm volatile(
      "mma.sync.aligned.m16n8k16.row.col.f32.bf16.bf16.f32 "
      "{%0,%1,%2,%3}, {%4,%5,%6,%7}, {%8,%9}, {%0,%1,%2,%3};\n"
      : "+f"(c[0]), "+f"(c[1]), "+f"(c[2]), "+f"(c[3])
      : "r"(a[0]), "r"(a[1]), "r"(a[2]), "r"(a[3]), "r"(b0), "r"(b1));
}

__device__ __forceinline__ void ldsm4(uint32_t& r0, uint32_t& r1, uint32_t& r2, uint32_t& r3,
                                      uint32_t addr) {
  asm volatile("ldmatrix.sync.aligned.m8n8.x4.shared.b16 {%0,%1,%2,%3}, [%4];"
               : "=r"(r0), "=r"(r1), "=r"(r2), "=r"(r3) : "r"(addr));
}

#define SSTR 40

__global__ void __launch_bounds__(256, 2)
k_gemm_mma(const float* __restrict__ Ain, int K,
           const float* __restrict__ as_, const float* __restrict__ ad_) {
  const float* A = Ain ? Ain : g_x;
  __shared__ __nv_bfloat16 sAhi[128 * SSTR];
  __shared__ __nv_bfloat16 sAlo[128 * SSTR];
  __shared__ __nv_bfloat16 sBhi[128 * SSTR];
  __shared__ __nv_bfloat16 sBlo[128 * SSTR];

  const int bm = blockIdx.y * 128;
  const int bn = blockIdx.x * 128;
  const int tid = threadIdx.x;
  const int warp = tid >> 5, lane = tid & 31;
  const int wm = warp >> 1, wn = warp & 1;     // 4x2 warp grid
  const int gid = lane >> 2, tig = lane & 3;

  // ldmatrix lane-address components
  const int lt = lane >> 3, lr = lane & 7;
  const int a_row = (lt & 1) * 8 + lr;         // within 16-row A tile
  const int a_col = (lt >> 1) * 8;             // k offset 0/8
  const int b_row = (lt >> 1) * 8 + lr;        // within 16-row (n) B pair
  const int b_col = (lt & 1) * 8;              // k offset 0/8

  const uint32_t uAhi = (uint32_t)__cvta_generic_to_shared(sAhi);
  const uint32_t uAlo = (uint32_t)__cvta_generic_to_shared(sAlo);
  const uint32_t uBhi = (uint32_t)__cvta_generic_to_shared(sBhi);
  const uint32_t uBlo = (uint32_t)__cvta_generic_to_shared(sBlo);

  float acc[2][8][4];
#pragma unroll
  for (int i = 0; i < 2; i++)
#pragma unroll
    for (int j = 0; j < 8; j++)
#pragma unroll
      for (int q = 0; q < 4; q++) acc[i][j][q] = 0.f;

  for (int k0 = 0; k0 < K; k0 += 32) {
    // --- stage A chunk [128][32] fp32 -> split bf16 hi/lo
#pragma unroll
    for (int it = 0; it < 4; it++) {
      int q = tid + 256 * it;
      int r = q >> 3, c = (q & 7) * 4;
      int gr = bm + r;
      float4 v = make_float4(0.f, 0.f, 0.f, 0.f);
      if (gr < NN) v = *(const float4*)(A + (size_t)gr * K + k0 + c);
      __nv_bfloat16 h0 = __float2bfloat16(v.x), h1 = __float2bfloat16(v.y);
      __nv_bfloat16 h2 = __float2bfloat16(v.z), h3 = __float2bfloat16(v.w);
      __nv_bfloat16 l0 = __float2bfloat16(v.x - __bfloat162float(h0));
      __nv_bfloat16 l1 = __float2bfloat16(v.y - __bfloat162float(h1));
      __nv_bfloat16 l2 = __float2bfloat16(v.z - __bfloat162float(h2));
      __nv_bfloat16 l3 = __float2bfloat16(v.w - __bfloat162float(h3));
      __nv_bfloat162* dh = (__nv_bfloat162*)&sAhi[r * SSTR + c];
      __nv_bfloat162* dl = (__nv_bfloat162*)&sAlo[r * SSTR + c];
      dh[0] = __halves2bfloat162(h0, h1);
      dh[1] = __halves2bfloat162(h2, h3);
      dl[0] = __halves2bfloat162(l0, l1);
      dl[1] = __halves2bfloat162(l2, l3);
    }
    // --- stage B chunk: g_bthi/lo [256][K] -> sB [n(128)][k(32)]
#pragma unroll
    for (int it = 0; it < 2; it++) {
      int q = tid + 256 * it;
      int nl = q >> 2, kq = (q & 3) * 8;
      const uint4* srch = (const uint4*)&g_bthi[(bn + nl) * K + k0 + kq];
      const uint4* srcl = (const uint4*)&g_btlo[(bn + nl) * K + k0 + kq];
      *(uint4*)&sBhi[nl * SSTR + kq] = *srch;
      *(uint4*)&sBlo[nl * SSTR + kq] = *srcl;
    }
    __syncthreads();

#pragma unroll
    for (int ks = 0; ks < 2; ks++) {
      const int kb = ks * 16;
      uint32_t ahi[2][4], alo[2][4];
#pragma unroll
      for (int i = 0; i < 2; i++) {
        uint32_t off = (uint32_t)(((wm * 32 + i * 16 + a_row) * SSTR + kb + a_col) * 2);
        ldsm4(ahi[i][0], ahi[i][1], ahi[i][2], ahi[i][3], uAhi + off);
        ldsm4(alo[i][0], alo[i][1], alo[i][2], alo[i][3], uAlo + off);
      }
#pragma unroll
      for (int jj = 0; jj < 4; jj++) {
        uint32_t off = (uint32_t)(((wn * 64 + jj * 16 + b_row) * SSTR + kb + b_col) * 2);
        uint32_t bh0, bh1, bh2, bh3, bl0, bl1, bl2, bl3;
        ldsm4(bh0, bh1, bh2, bh3, uBhi + off);
        ldsm4(bl0, bl1, bl2, bl3, uBlo + off);
#pragma unroll
        for (int i = 0; i < 2; i++) {
          mma_bf16(acc[i][jj * 2],     ahi[i], bh0, bh1);
          mma_bf16(acc[i][jj * 2],     ahi[i], bl0, bl1);
          mma_bf16(acc[i][jj * 2],     alo[i], bh0, bh1);
          mma_bf16(acc[i][jj * 2 + 1], ahi[i], bh2, bh3);
          mma_bf16(acc[i][jj * 2 + 1], ahi[i], bl2, bl3);
          mma_bf16(acc[i][jj * 2 + 1], alo[i], bh2, bh3);
        }
      }
    }
    __syncthreads();
  }

  // --- epilogue 1: write fp16 h
#pragma unroll
  for (int i = 0; i < 2; i++) {
#pragma unroll
    for (int j = 0; j < 8; j++) {
      int row = bm + wm * 32 + i * 16 + gid;
      int col = bn + wn * 64 + j * 8 + 2 * tig;
      __half2 p01 = __floats2half2_rn(acc[i][j][0], acc[i][j][1]);
      __half2 p23 = __floats2half2_rn(acc[i][j][2], acc[i][j][3]);
      if (row < NN)
        *(__half2*)(g_h16 + (size_t)row * 256 + col) = p01;
      if (row + 8 < NN)
        *(__half2*)(g_h16 + (size_t)(row + 8) * 256 + col) = p23;
    }
  }

  // --- epilogue 2: fused attention logits for head = 2*bn + wn
  {
    const int head = blockIdx.x * 2 + wn;
    float wa[16], wd[16];
#pragma unroll
    for (int j = 0; j < 8; j++) {
      int c = j * 8 + 2 * tig;
      wa[j * 2 + 0] = as_[head * 64 + c];
      wa[j * 2 + 1] = as_[head * 64 + c + 1];
      wd[j * 2 + 0] = ad_[head * 64 + c];
      wd[j * 2 + 1] = ad_[head * 64 + c + 1];
    }
#pragma unroll
    for (int i = 0; i < 2; i++) {
      float s0 = 0.f, s1 = 0.f, d0 = 0.f, d1 = 0.f;
#pragma unroll
      for (int j = 0; j < 8; j++) {
        s0 = fmaf(acc[i][j][0], wa[j * 2], fmaf(acc[i][j][1], wa[j * 2 + 1], s0));
        s1 = fmaf(acc[i][j][2], wa[j * 2], fmaf(acc[i][j][3], wa[j * 2 + 1], s1));
        d0 = fmaf(acc[i][j][0], wd[j * 2], fmaf(acc[i][j][1], wd[j * 2 + 1], d0));
        d1 = fmaf(acc[i][j][2], wd[j * 2], fmaf(acc[i][j][3], wd[j * 2 + 1], d1));
      }
#pragma unroll
      for (int o = 1; o <= 2; o <<= 1) {
        s0 += __shfl_xor_sync(0xffffffffu, s0, o);
        s1 += __shfl_xor_sync(0xffffffffu, s1, o);
        d0 += __shfl_xor_sync(0xffffffffu, d0, o);
        d1 += __shfl_xor_sync(0xffffffffu, d1, o);
      }
      if (tig == 0) {
        int row = bm + wm * 32 + i * 16 + gid;
        if (row < NN)     { g_als[row * 4 + head] = s0; g_ald[row * 4 + head] = d0; }
        if (row + 8 < NN) { g_als[(row + 8) * 4 + head] = s1; g_ald[(row + 8) * 4 + head] = d1; }
      }
    }
  }
}

// ---------------- softmax + aggregation: one warp per dst node ----------------
// Max-shift skipped: logits are O(1) by construction -> exp cannot overflow.
// Per-edge alpha cached in shared memory (gmem fallback for deg > 64).
__device__ __forceinline__ float leaky(float v) { return v >= 0.f ? v : 0.2f * v; }

#define ACAP 64

__global__ void __launch_bounds__(256)
k_agg(const float* __restrict__ bias, float* __restrict__ outp, int do_relu) {
  __shared__ float4 s_alpha[8][ACAP];
  int warp = (blockIdx.x * blockDim.x + threadIdx.x) >> 5;
  int wip = threadIdx.x >> 5;
  int lane = threadIdx.x & 31;
  if (warp >= NN) return;
  float* op = outp ? outp : g_x;
  const int n = warp;
  const int beg = g_offs[n], end = g_offs[n + 1];

  const float4 ald = *(const float4*)&g_ald[n * 4];

  float d0 = 0.f, d1 = 0.f, d2 = 0.f, d3 = 0.f;
  for (int e = beg + lane; e < end; e += 32) {
    int s = g_ssrc[e];
    float4 als = *(const float4*)&g_als[s * 4];
    float p0 = __expf(leaky(als.x + ald.x));
    float p1 = __expf(leaky(als.y + ald.y));
    float p2 = __expf(leaky(als.z + ald.z));
    float p3 = __expf(leaky(als.w + ald.w));
    d0 += p0; d1 += p1; d2 += p2; d3 += p3;
    int idx = e - beg;
    float4 pv = make_float4(p0, p1, p2, p3);
    if (idx < ACAP) s_alpha[wip][idx] = pv;
    else            *(float4*)&g_alpha[(size_t)e * 4] = pv;
  }
#pragma unroll
  for (int o = 16; o; o >>= 1) {
    d0 += __shfl_xor_sync(0xffffffffu, d0, o);
    d1 += __shfl_xor_sync(0xffffffffu, d1, o);
    d2 += __shfl_xor_sync(0xffffffffu, d2, o);
    d3 += __shfl_xor_sync(0xffffffffu, d3, o);
  }
  __syncwarp();

  const bool hs = (lane & 16) != 0;
  const float rA = 1.0f / (hs ? d1 : d0);
  const float rB = 1.0f / (hs ? d3 : d2);

  // phase B: warp-serial over edges (unroll 2); lanes cover 256 feats.
  float4 acc0 = make_float4(0.f, 0.f, 0.f, 0.f);
  float4 acc1 = make_float4(0.f, 0.f, 0.f, 0.f);
  const int deg = end - beg;
  int idx = 0;
  for (; idx + 1 < deg; idx += 2) {
    int sA_ = g_ssrc[beg + idx];
    int sB_ = g_ssrc[beg + idx + 1];
    float4 pA = (idx < ACAP) ? s_alpha[wip][idx] : *(const float4*)&g_alpha[(size_t)(beg + idx) * 4];
    float4 pB = (idx + 1 < ACAP) ? s_alpha[wip][idx + 1] : *(const float4*)&g_alpha[(size_t)(beg + idx + 1) * 4];
    const uint2* hpA = (const uint2*)(g_h16 + (size_t)sA_ * 256);
    const uint2* hpB = (const uint2*)(g_h16 + (size_t)sB_ * 256);
    uint2 rA0 = __ldg(hpA + lane);
    uint2 rA1 = __ldg(hpA + 32 + lane);
    uint2 rB0 = __ldg(hpB + lane);
    uint2 rB1 = __ldg(hpB + 32 + lane);
    float aA0 = (hs ? pA.y : pA.x) * rA;
    float aA1 = (hs ? pA.w : pA.z) * rB;
    float aB0 = (hs ? pB.y : pB.x) * rA;
    float aB1 = (hs ? pB.w : pB.z) * rB;
    float2 f;
    f = __half22float2(*(const __half2*)&rA0.x); acc0.x = fmaf(f.x, aA0, acc0.x); acc0.y = fmaf(f.y, aA0, acc0.y);
    f = __half22float2(*(const __half2*)&rA0.y); acc0.z = fmaf(f.x, aA0, acc0.z); acc0.w = fmaf(f.y, aA0, acc0.w);
    f = __half22float2(*(const __half2*)&rA1.x); acc1.x = fmaf(f.x, aA1, acc1.x); acc1.y = fmaf(f.y, aA1, acc1.y);
    f = __half22float2(*(const __half2*)&rA1.y); acc1.z = fmaf(f.x, aA1, acc1.z); acc1.w = fmaf(f.y, aA1, acc1.w);
    f = __half22float2(*(const __half2*)&rB0.x); acc0.x = fmaf(f.x, aB0, acc0.x); acc0.y = fmaf(f.y, aB0, acc0.y);
    f = __half22float2(*(const __half2*)&rB0.y); acc0.z = fmaf(f.x, aB0, acc0.z); acc0.w = fmaf(f.y, aB0, acc0.w);
    f = __half22float2(*(const __half2*)&rB1.x); acc1.x = fmaf(f.x, aB1, acc1.x); acc1.y = fmaf(f.y, aB1, acc1.y);
    f = __half22float2(*(const __half2*)&rB1.y); acc1.z = fmaf(f.x, aB1, acc1.z); acc1.w = fmaf(f.y, aB1, acc1.w);
  }
  if (idx < deg) {
    int s = g_ssrc[beg + idx];
    float4 p = (idx < ACAP) ? s_alpha[wip][idx] : *(const float4*)&g_alpha[(size_t)(beg + idx) * 4];
    float a0 = (hs ? p.y : p.x) * rA;
    float a1 = (hs ? p.w : p.z) * rB;
    const uint2* hp = (const uint2*)(g_h16 + (size_t)s * 256);
    uint2 r0 = __ldg(hp + lane);
    uint2 r1 = __ldg(hp + 32 + lane);
    float2 f;
    f = __half22float2(*(const __half2*)&r0.x); acc0.x = fmaf(f.x, a0, acc0.x); acc0.y = fmaf(f.y, a0, acc0.y);
    f = __half22float2(*(const __half2*)&r0.y); acc0.z = fmaf(f.x, a0, acc0.z); acc0.w = fmaf(f.y, a0, acc0.w);
    f = __half22float2(*(const __half2*)&r1.x); acc1.x = fmaf(f.x, a1, acc1.x); acc1.y = fmaf(f.y, a1, acc1.y);
    f = __half22float2(*(const __half2*)&r1.y); acc1.z = fmaf(f.x, a1, acc1.z); acc1.w = fmaf(f.y, a1, acc1.w);
  }

  float4 t;
  t.x = acc0.x + acc1.x; t.y = acc0.y + acc1.y;
  t.z = acc0.z + acc1.z; t.w = acc0.w + acc1.w;
  t.x += __shfl_xor_sync(0xffffffffu, t.x, 16);
  t.y += __shfl_xor_sync(0xffffffffu, t.y, 16);
  t.z += __shfl_xor_sync(0xffffffffu, t.z, 16);
  t.w += __shfl_xor_sync(0xffffffffu, t.w, 16);
  if (lane < 16) {
    const float4 b4 = *(const float4*)(bias + lane * 4);
    float4 o;
    o.x = t.x * 0.25f + b4.x;
    o.y = t.y * 0.25f + b4.y;
    o.z = t.z * 0.25f + b4.z;
    o.w = t.w * 0.25f + b4.w;
    if (do_relu) {
      o.x = fmaxf(o.x, 0.f); o.y = fmaxf(o.y, 0.f);
      o.z = fmaxf(o.z, 0.f); o.w = fmaxf(o.w, 0.f);
    }
    *(float4*)(op + (size_t)n * 64 + lane * 4) = o;
  }
}

// ---------------- node MLP heads + pooling ----------------
__device__ __forceinline__ float sigmoidf_(float x) { return 1.0f / (1.0f + __expf(-x)); }

__global__ void k_node_mlp(const float* __restrict__ emb, const int* __restrict__ batch,
                           const float* __restrict__ aw1, const float* __restrict__ ab1,
                           const float* __restrict__ aw2, const float* __restrict__ ab2,
                           const float* __restrict__ rw1, const float* __restrict__ rb1,
                           const float* __restrict__ rw2, const float* __restrict__ rb2,
                           const float* __restrict__ cw1, const float* __restrict__ cb1,
                           const float* __restrict__ cw2, const float* __restrict__ cb2,
                           float* __restrict__ anomaly, float* __restrict__ risk,
                           float* __restrict__ resource) {
  int warp = (blockIdx.x * blockDim.x + threadIdx.x) >> 5;
  int lane = threadIdx.x & 31;
  if (warp >= NN) return;
  int n = warp;
  float e0 = emb[(size_t)n * 64 + lane];
  float e1 = emb[(size_t)n * 64 + 32 + lane];

  float ha = ab1[lane], hr = rb1[lane], hc = cb1[lane];
#pragma unroll
  for (int k = 0; k < 32; k++) {
    float ek = __shfl_sync(0xffffffffu, e0, k);
    ha = fmaf(ek, aw1[k * 32 + lane], ha);
    hr = fmaf(ek, rw1[k * 32 + lane], hr);
    hc = fmaf(ek, cw1[k * 32 + lane], hc);
  }
#pragma unroll
  for (int k = 0; k < 32; k++) {
    float ek = __shfl_sync(0xffffffffu, e1, k);
    ha = fmaf(ek, aw1[(k + 32) * 32 + lane], ha);
    hr = fmaf(ek, rw1[(k + 32) * 32 + lane], hr);
    hc = fmaf(ek, cw1[(k + 32) * 32 + lane], hc);
  }
  ha = fmaxf(ha, 0.f); hr = fmaxf(hr, 0.f); hc = fmaxf(hc, 0.f);

  float va = ha * aw2[lane];
  float vr = hr * rw2[lane];
#pragma unroll
  for (int o = 16; o; o >>= 1) {
    va += __shfl_xor_sync(0xffffffffu, va, o);
    vr += __shfl_xor_sync(0xffffffffu, vr, o);
  }
  if (lane == 0) {
    anomaly[n] = sigmoidf_(va + ab2[0]);
    risk[n]    = sigmoidf_(vr + rb2[0]);
  }
#pragma unroll
  for (int o5 = 0; o5 < 5; o5++) {
    float vc = hc * cw2[lane * 5 + o5];
#pragma unroll
    for (int o = 16; o; o >>= 1) vc += __shfl_xor_sync(0xffffffffu, vc, o);
    if (lane == 0) resource[(size_t)n * 5 + o5] = vc + cb2[o5];
  }

  int g = batch[n];
  atomicAdd(&g_psum[g * 64 + lane], e0);
  atomicAdd(&g_psum[g * 64 + 32 + lane], e1);
  if (lane == 0) atomicAdd(&g_pcnt[g], 1.0f);
}

__global__ void k_graph_head(const float* __restrict__ gw1, const float* __restrict__ gb1,
                             const float* __restrict__ gw2, const float* __restrict__ gb2,
                             float* __restrict__ glog) {
  int g = blockIdx.x;
  int lane = threadIdx.x;
  float rc = 1.0f / fmaxf(g_pcnt[g], 1.0f);
  float hid = gb1[lane];
#pragma unroll
  for (int c = 0; c < 64; c++)
    hid = fmaf(g_psum[g * 64 + c] * rc, gw1[c * 32 + lane], hid);
  hid = fmaxf(hid, 0.f);
#pragma unroll
  for (int o4 = 0; o4 < 4; o4++) {
    float v = hid * gw2[lane * 4 + o4];
#pragma unroll
    for (int o = 16; o; o >>= 1) v += __shfl_xor_sync(0xffffffffu, v, o);
    if (lane == 0) glog[g * 4 + o4] = v + gb2[o4];
  }
}

// ---------------- launch ----------------
extern "C" void kernel_launch(void* const* d_in, const int* in_sizes, int n_in,
                              void* d_out, int out_size) {
  const float* x    = (const float*)d_in[0];
  const int*   ei   = (const int*)d_in[1];
  const int*   batch= (const int*)d_in[2];
  const float* W1   = (const float*)d_in[3];
  const float* as1  = (const float*)d_in[4];
  const float* ad1  = (const float*)d_in[5];
  const float* b1   = (const float*)d_in[6];
  const float* W2   = (const float*)d_in[7];
  const float* as2  = (const float*)d_in[8];
  const float* ad2  = (const float*)d_in[9];
  const float* b2   = (const float*)d_in[10];
  const float* W3   = (const float*)d_in[11];
  const float* as3  = (const float*)d_in[12];
  const float* ad3  = (const float*)d_in[13];
  const float* b3   = (const float*)d_in[14];
  const float* aw1  = (const float*)d_in[15];
  const float* ab1  = (const float*)d_in[16];
  const float* aw2  = (const float*)d_in[17];
  const float* ab2  = (const float*)d_in[18];
  const float* rw1  = (const float*)d_in[19];
  const float* rb1  = (const float*)d_in[20];
  const float* rw2  = (const float*)d_in[21];
  const float* rb2  = (const float*)d_in[22];
  const float* cw1  = (const float*)d_in[23];
  const float* cb1  = (const float*)d_in[24];
  const float* cw2  = (const float*)d_in[25];
  const float* cb2  = (const float*)d_in[26];
  const float* gw1  = (const float*)d_in[27];
  const float* gb1  = (const float*)d_in[28];
  const float* gw2  = (const float*)d_in[29];
  const float* gb2  = (const float*)d_in[30];

  float* out      = (float*)d_out;
  float* emb      = out;                        // N*64
  float* anomaly  = out + (size_t)NN * 64;      // N
  float* risk     = anomaly + NN;               // N
  float* resource = risk + NN;                  // N*5
  float* glog     = resource + (size_t)NN * 5;  // G*4

  dim3 gg(2, (NN + 127) / 128);
  int agg_grid = (NN * 32 + 255) / 256;

  k_init<<<(NN + 255) / 256, 256>>>();
  k_degree<<<(NE + 255) / 256, 256>>>(ei);
  k_bsplit<<<(256 * 128 + 255) / 256, 256>>>(W1, 128);
  k_gemm_mma<<<gg, 256>>>(x, 128, as1, ad1);
  k_scan<<<1, 1024>>>();
  k_scatter<<<(NE2 + 255) / 256, 256>>>(ei);
  k_agg<<<agg_grid, 256>>>(b1, nullptr, 1);

  // layer 2 (K=64)
  k_bsplit<<<(256 * 64 + 255) / 256, 256>>>(W2, 64);
  k_gemm_mma<<<gg, 256>>>(nullptr, 64, as2, ad2);
  k_agg<<<agg_grid, 256>>>(b2, nullptr, 1);
  // layer 3 (K=64)
  k_bsplit<<<(256 * 64 + 255) / 256, 256>>>(W3, 64);
  k_gemm_mma<<<gg, 256>>>(nullptr, 64, as3, ad3);
  k_agg<<<agg_grid, 256>>>(b3, emb, 0);

  // heads
  k_node_mlp<<<agg_grid, 256>>>(emb, batch, aw1, ab1, aw2, ab2,
                                rw1, rb1, rw2, rb2, cw1, cb1, cw2, cb2,
                                anomaly, risk, resource);
  k_graph_head<<<NG, 32>>>(gw1, gb1, gw2, gb2, glog);
}